// round 1
// baseline (speedup 1.0000x reference)
#include <cuda_runtime.h>

#define BB 32
#define CL 1024
#define QL 128
#define HH 512
#define NEG (-1e30f)

// ---- scratch (device globals; no allocations allowed) ----
__device__ float g_cw1[BB * CL];                    // C @ w1
__device__ float g_qw2[BB * QL];                    // Q @ w2
__device__ float g_S[(size_t)BB * CL * QL];         // raw scores
__device__ float g_Srow[(size_t)BB * CL * QL];      // row softmax
__device__ float g_Scol[(size_t)BB * CL * QL];      // col softmax
__device__ float g_T[(size_t)BB * QL * HH];         // S_col^T @ C

// ---------------------------------------------------------------------------
// K1: cw1[b,i] = C[b,i]·w1 ; qw2[b,j] = Q[b,j]·w2   (warp per row)
// ---------------------------------------------------------------------------
__global__ void k_dots(const float* __restrict__ C, const float* __restrict__ Q,
                       const float* __restrict__ w) {
    int warp = (blockIdx.x * blockDim.x + threadIdx.x) >> 5;
    int lane = threadIdx.x & 31;
    const int nC = BB * CL;
    if (warp >= nC + BB * QL) return;
    const float* row;
    const float* wp;
    float* out;
    if (warp < nC) {
        row = C + (size_t)warp * HH; wp = w;       out = g_cw1 + warp;
    } else {
        int r = warp - nC;
        row = Q + (size_t)r * HH;    wp = w + HH;  out = g_qw2 + r;
    }
    const float4* r4 = (const float4*)row;
    const float4* w4 = (const float4*)wp;
    float acc = 0.f;
#pragma unroll
    for (int q = 0; q < 4; q++) {
        float4 v = r4[lane + 32 * q];
        float4 ww = w4[lane + 32 * q];
        acc += v.x * ww.x + v.y * ww.y + v.z * ww.z + v.w * ww.w;
    }
#pragma unroll
    for (int off = 16; off; off >>= 1) acc += __shfl_xor_sync(0xffffffffu, acc, off);
    if (lane == 0) *out = acc;
}

// ---------------------------------------------------------------------------
// K2: S[b,i,j] = sum_h C[b,i,h]*w3[h]*Q[b,j,h] + cw1 + qw2 + b0
//     64x64 tile, 256 threads, 4x4 microtile, K-chunk 16
// ---------------------------------------------------------------------------
__global__ __launch_bounds__(256) void k_sgemm(const float* __restrict__ C,
                                               const float* __restrict__ Q,
                                               const float* __restrict__ w,
                                               const float* __restrict__ bias) {
    __shared__ float As[16][68];  // [k][m=i]
    __shared__ float Bs[16][68];  // [k][n=j]
    int b = blockIdx.z;
    int i0 = blockIdx.x * 64, j0 = blockIdx.y * 64;
    int t = threadIdx.x, tx = t & 15, ty = t >> 4;
    const float* w3 = w + 2 * HH;
    const float* Cb = C + ((size_t)b * CL + i0) * HH;
    const float* Qb = Q + ((size_t)b * QL + j0) * HH;
    int lr = t >> 2, lk = (t & 3) << 2;
    float acc[4][4] = {};
    for (int kk = 0; kk < HH; kk += 16) {
        float4 a = *(const float4*)(Cb + (size_t)lr * HH + kk + lk);
        float4 wv = *(const float4*)(w3 + kk + lk);
        As[lk + 0][lr] = a.x * wv.x; As[lk + 1][lr] = a.y * wv.y;
        As[lk + 2][lr] = a.z * wv.z; As[lk + 3][lr] = a.w * wv.w;
        float4 q = *(const float4*)(Qb + (size_t)lr * HH + kk + lk);
        Bs[lk + 0][lr] = q.x; Bs[lk + 1][lr] = q.y;
        Bs[lk + 2][lr] = q.z; Bs[lk + 3][lr] = q.w;
        __syncthreads();
#pragma unroll
        for (int k = 0; k < 16; k++) {
            float4 bv = *(const float4*)&Bs[k][tx * 4];
            float4 av = *(const float4*)&As[k][ty * 4];
            float am[4] = {av.x, av.y, av.z, av.w};
#pragma unroll
            for (int mi = 0; mi < 4; mi++) {
                acc[mi][0] += am[mi] * bv.x; acc[mi][1] += am[mi] * bv.y;
                acc[mi][2] += am[mi] * bv.z; acc[mi][3] += am[mi] * bv.w;
            }
        }
        __syncthreads();
    }
    float b0 = bias[0];
#pragma unroll
    for (int mi = 0; mi < 4; mi++) {
        int i = i0 + ty * 4 + mi;
        float cw = g_cw1[b * CL + i] + b0;
        int j = j0 + tx * 4;
        float4 o;
        o.x = acc[mi][0] + cw + g_qw2[b * QL + j + 0];
        o.y = acc[mi][1] + cw + g_qw2[b * QL + j + 1];
        o.z = acc[mi][2] + cw + g_qw2[b * QL + j + 2];
        o.w = acc[mi][3] + cw + g_qw2[b * QL + j + 3];
        *(float4*)&g_S[((size_t)b * CL + i) * QL + j] = o;
    }
}

// ---------------------------------------------------------------------------
// K3: row softmax over j with Q_mask (warp per (b,i) row, 4 j per lane)
// ---------------------------------------------------------------------------
__global__ void k_rowsm(const int* __restrict__ qmask) {
    int warp = (blockIdx.x * blockDim.x + threadIdx.x) >> 5;
    int lane = threadIdx.x & 31;
    if (warp >= BB * CL) return;
    int b = warp / CL;
    const float* s = g_S + (size_t)warp * QL;
    const int* qm = qmask + b * QL;
    float v[4];
    float m = NEG;
#pragma unroll
    for (int q = 0; q < 4; q++) {
        int j = lane + 32 * q;
        v[q] = qm[j] ? s[j] : NEG;
        m = fmaxf(m, v[q]);
    }
#pragma unroll
    for (int off = 16; off; off >>= 1) m = fmaxf(m, __shfl_xor_sync(0xffffffffu, m, off));
    float sum = 0.f;
#pragma unroll
    for (int q = 0; q < 4; q++) { v[q] = expf(v[q] - m); sum += v[q]; }
#pragma unroll
    for (int off = 16; off; off >>= 1) sum += __shfl_xor_sync(0xffffffffu, sum, off);
    float inv = 1.f / sum;
#pragma unroll
    for (int q = 0; q < 4; q++) g_Srow[(size_t)warp * QL + lane + 32 * q] = v[q] * inv;
}

// ---------------------------------------------------------------------------
// K4: col softmax over i with C_mask. block (32,8): tx->j, ty strides i
// ---------------------------------------------------------------------------
__global__ void k_colsm(const int* __restrict__ cmask) {
    int b = blockIdx.y;
    int j = blockIdx.x * 32 + threadIdx.x;
    int ty = threadIdx.y;
    __shared__ float red[8][33];
    const int* cm = cmask + b * CL;
    const float* S = g_S + (size_t)b * CL * QL;
    float m = NEG;
    for (int i = ty; i < CL; i += 8) {
        float v = cm[i] ? S[(size_t)i * QL + j] : NEG;
        m = fmaxf(m, v);
    }
    red[ty][threadIdx.x] = m;
    __syncthreads();
    m = NEG;
#pragma unroll
    for (int y = 0; y < 8; y++) m = fmaxf(m, red[y][threadIdx.x]);
    __syncthreads();
    float s = 0.f;
    for (int i = ty; i < CL; i += 8) {
        float v = cm[i] ? S[(size_t)i * QL + j] : NEG;
        s += expf(v - m);
    }
    red[ty][threadIdx.x] = s;
    __syncthreads();
    s = 0.f;
#pragma unroll
    for (int y = 0; y < 8; y++) s += red[y][threadIdx.x];
    float inv = 1.f / s;
    float* Sc = g_Scol + (size_t)b * CL * QL;
    for (int i = ty; i < CL; i += 8) {
        float v = cm[i] ? S[(size_t)i * QL + j] : NEG;
        Sc[(size_t)i * QL + j] = expf(v - m) * inv;
    }
}

// ---------------------------------------------------------------------------
// K5: T[b,j,h] = sum_i Scol[b,i,j] * C[b,i,h]   (M=128 j, N=512 h, K=1024 i)
// ---------------------------------------------------------------------------
__global__ __launch_bounds__(256) void k_tgemm(const float* __restrict__ C) {
    __shared__ float As[16][68];  // [k][m=j]
    __shared__ float Bs[16][68];  // [k][n=h]
    int b = blockIdx.z;
    int j0 = blockIdx.x * 64, h0 = blockIdx.y * 64;
    int t = threadIdx.x, tx = t & 15, ty = t >> 4;
    int ln = t & 63, lkb = t >> 6;
    const float* Sc = g_Scol + (size_t)b * CL * QL;
    const float* Cb = C + (size_t)b * CL * HH;
    float acc[4][4] = {};
    for (int kk = 0; kk < CL; kk += 16) {
#pragma unroll
        for (int q = 0; q < 4; q++) {
            int k = lkb + 4 * q;
            As[k][ln] = Sc[(size_t)(kk + k) * QL + j0 + ln];
            Bs[k][ln] = Cb[(size_t)(kk + k) * HH + h0 + ln];
        }
        __syncthreads();
#pragma unroll
        for (int k = 0; k < 16; k++) {
            float4 bv = *(const float4*)&Bs[k][tx * 4];
            float4 av = *(const float4*)&As[k][ty * 4];
            float am[4] = {av.x, av.y, av.z, av.w};
#pragma unroll
            for (int mi = 0; mi < 4; mi++) {
                acc[mi][0] += am[mi] * bv.x; acc[mi][1] += am[mi] * bv.y;
                acc[mi][2] += am[mi] * bv.z; acc[mi][3] += am[mi] * bv.w;
            }
        }
        __syncthreads();
    }
#pragma unroll
    for (int mi = 0; mi < 4; mi++) {
        int j = j0 + ty * 4 + mi;
        float4 o = make_float4(acc[mi][0], acc[mi][1], acc[mi][2], acc[mi][3]);
        *(float4*)&g_T[((size_t)b * QL + j) * HH + h0 + tx * 4] = o;
    }
}

// ---------------------------------------------------------------------------
// K6: fused A = Srow@Q and Bm = Srow@T (shared left operand, K=128),
//     epilogue writes concat(C, A, C*A, C*Bm)
// ---------------------------------------------------------------------------
__global__ __launch_bounds__(256) void k_out(const float* __restrict__ C,
                                             const float* __restrict__ Q,
                                             float* __restrict__ out) {
    __shared__ float Ss[16][68];  // [k=j][m=i]
    __shared__ float Qs[16][68];  // [k][n=h]
    __shared__ float Ts[16][68];  // [k][n=h]
    int b = blockIdx.z;
    int i0 = blockIdx.x * 64, h0 = blockIdx.y * 64;
    int t = threadIdx.x, tx = t & 15, ty = t >> 4;
    int lr = t >> 2, lk = (t & 3) << 2;
    int ln = t & 63, lkb = t >> 6;
    const float* Sr = g_Srow + ((size_t)b * CL + i0) * QL;
    const float* Qb = Q + (size_t)b * QL * HH;
    const float* Tb = g_T + (size_t)b * QL * HH;
    float accA[4][4] = {}, accB[4][4] = {};
    for (int kk = 0; kk < QL; kk += 16) {
        float4 sv = *(const float4*)(Sr + (size_t)lr * QL + kk + lk);
        Ss[lk + 0][lr] = sv.x; Ss[lk + 1][lr] = sv.y;
        Ss[lk + 2][lr] = sv.z; Ss[lk + 3][lr] = sv.w;
#pragma unroll
        for (int q = 0; q < 4; q++) {
            int k = lkb + 4 * q;
            Qs[k][ln] = Qb[(size_t)(kk + k) * HH + h0 + ln];
            Ts[k][ln] = Tb[(size_t)(kk + k) * HH + h0 + ln];
        }
        __syncthreads();
#pragma unroll
        for (int k = 0; k < 16; k++) {
            float4 qv = *(const float4*)&Qs[k][tx * 4];
            float4 tv = *(const float4*)&Ts[k][tx * 4];
            float4 av = *(const float4*)&Ss[k][ty * 4];
            float am[4] = {av.x, av.y, av.z, av.w};
#pragma unroll
            for (int mi = 0; mi < 4; mi++) {
                accA[mi][0] += am[mi] * qv.x; accA[mi][1] += am[mi] * qv.y;
                accA[mi][2] += am[mi] * qv.z; accA[mi][3] += am[mi] * qv.w;
                accB[mi][0] += am[mi] * tv.x; accB[mi][1] += am[mi] * tv.y;
                accB[mi][2] += am[mi] * tv.z; accB[mi][3] += am[mi] * tv.w;
            }
        }
        __syncthreads();
    }
#pragma unroll
    for (int mi = 0; mi < 4; mi++) {
        int i = i0 + ty * 4 + mi;
        int h = h0 + tx * 4;
        float4 c = *(const float4*)(C + ((size_t)b * CL + i) * HH + h);
        float* ob = out + ((size_t)b * CL + i) * (4 * HH);
        float4 a = make_float4(accA[mi][0], accA[mi][1], accA[mi][2], accA[mi][3]);
        float4 bm = make_float4(accB[mi][0], accB[mi][1], accB[mi][2], accB[mi][3]);
        *(float4*)(ob + h) = c;
        *(float4*)(ob + HH + h) = a;
        *(float4*)(ob + 2 * HH + h) = make_float4(c.x * a.x, c.y * a.y, c.z * a.z, c.w * a.w);
        *(float4*)(ob + 3 * HH + h) = make_float4(c.x * bm.x, c.y * bm.y, c.z * bm.z, c.w * bm.w);
    }
}

// ---------------------------------------------------------------------------
extern "C" void kernel_launch(void* const* d_in, const int* in_sizes, int n_in,
                              void* d_out, int out_size) {
    const float* C = (const float*)d_in[0];
    const float* Q = (const float*)d_in[1];
    const int* cmask = (const int*)d_in[2];
    const int* qmask = (const int*)d_in[3];
    const float* w = (const float*)d_in[4];
    const float* bias = (const float*)d_in[5];
    float* out = (float*)d_out;

    // K1: 36864 rows, warp per row -> 4608 blocks of 256
    k_dots<<<4608, 256>>>(C, Q, w);
    // K2: S gemm. tiles: 16 x 2 x 32
    k_sgemm<<<dim3(16, 2, 32), 256>>>(C, Q, w, bias);
    // K3: 32768 rows, 8 warps/block
    k_rowsm<<<4096, 256>>>(qmask);
    // K4: 4 j-groups x 32 batches
    k_colsm<<<dim3(QL / 32, BB), dim3(32, 8)>>>(cmask);
    // K5: T gemm: 2 x 8 x 32
    k_tgemm<<<dim3(2, 8, 32), 256>>>(C);
    // K6: fused output: 16 x 8 x 32
    k_out<<<dim3(16, 8, 32), 256>>>(C, Q, out);
}

// round 3
// speedup vs baseline: 1.3409x; 1.3409x over previous
#include <cuda_runtime.h>
#include <cstdint>

#define BB 32
#define CL 1024
#define QL 128
#define HH 512
#define NEG (-1e30f)

// ---- scratch (device globals; no allocations allowed) ----
__device__ float g_cw1[BB * CL];
__device__ float g_qw2[BB * QL];
__device__ float g_S[(size_t)BB * CL * QL];
__device__ float g_Srow[(size_t)BB * CL * QL];
__device__ float g_Scol[(size_t)BB * CL * QL];
__device__ float g_T[(size_t)BB * QL * HH];

__device__ __forceinline__ float tf32r(float x) {
    uint32_t u;
    asm("cvt.rna.tf32.f32 %0, %1;\n" : "=r"(u) : "f"(x));
    return __uint_as_float(u);
}

__device__ __forceinline__ void mma8(float* d, const uint32_t* a, const uint32_t* b) {
    asm volatile(
        "mma.sync.aligned.m16n8k8.row.col.f32.tf32.tf32.f32 "
        "{%0,%1,%2,%3},{%4,%5,%6,%7},{%8,%9},{%0,%1,%2,%3};\n"
        : "+f"(d[0]), "+f"(d[1]), "+f"(d[2]), "+f"(d[3])
        : "r"(a[0]), "r"(a[1]), "r"(a[2]), "r"(a[3]), "r"(b[0]), "r"(b[1]));
}

// ---------------------------------------------------------------------------
// K1: cw1[b,i] = C[b,i]·w1 ; qw2[b,j] = Q[b,j]·w2   (warp per row)
// ---------------------------------------------------------------------------
__global__ void k_dots(const float* __restrict__ C, const float* __restrict__ Q,
                       const float* __restrict__ w) {
    int warp = (blockIdx.x * blockDim.x + threadIdx.x) >> 5;
    int lane = threadIdx.x & 31;
    const int nC = BB * CL;
    if (warp >= nC + BB * QL) return;
    const float* row;
    const float* wp;
    float* out;
    if (warp < nC) {
        row = C + (size_t)warp * HH; wp = w;       out = g_cw1 + warp;
    } else {
        int r = warp - nC;
        row = Q + (size_t)r * HH;    wp = w + HH;  out = g_qw2 + r;
    }
    const float4* r4 = (const float4*)row;
    const float4* w4 = (const float4*)wp;
    float acc = 0.f;
#pragma unroll
    for (int q = 0; q < 4; q++) {
        float4 v = r4[lane + 32 * q];
        float4 ww = w4[lane + 32 * q];
        acc += v.x * ww.x + v.y * ww.y + v.z * ww.z + v.w * ww.w;
    }
#pragma unroll
    for (int off = 16; off; off >>= 1) acc += __shfl_xor_sync(0xffffffffu, acc, off);
    if (lane == 0) *out = acc;
}

// ---------------------------------------------------------------------------
// K2: S = (C*w3)@Q^T + cw1 + qw2 + b   via tf32 MMA
// block tile 128(i) x 64(j), K = h (512). A:[m][k], B:[n][k]
// ---------------------------------------------------------------------------
#define APAD 12
__global__ __launch_bounds__(256) void k_sgemm(const float* __restrict__ C,
                                               const float* __restrict__ Q,
                                               const float* __restrict__ w,
                                               const float* __restrict__ bias) {
    __shared__ float As[2][128][APAD];
    __shared__ float Bs[2][64][APAD];
    int b = blockIdx.z, i0 = blockIdx.x * 128, j0 = blockIdx.y * 64;
    int t = threadIdx.x, lane = t & 31, wid = t >> 5;
    int m0w = (wid & 3) * 32, n0w = (wid >> 2) * 32;
    int r = lane >> 2, c = lane & 3;
    const float* w3 = w + 2 * HH;
    const float* Cb = C + ((size_t)b * CL + i0) * HH;
    const float* Qb = Q + ((size_t)b * QL + j0) * HH;
    int ar = t >> 1, ak = (t & 1) * 4;

    float4 ra, rb, rw;
    ra = *(const float4*)(Cb + (size_t)ar * HH + ak);
    rw = *(const float4*)(w3 + ak);
    if (t < 128) rb = *(const float4*)(Qb + (size_t)(t >> 1) * HH + (t & 1) * 4);
    *(float4*)&As[0][ar][ak] =
        make_float4(tf32r(ra.x * rw.x), tf32r(ra.y * rw.y), tf32r(ra.z * rw.z), tf32r(ra.w * rw.w));
    if (t < 128)
        *(float4*)&Bs[0][t >> 1][(t & 1) * 4] =
            make_float4(tf32r(rb.x), tf32r(rb.y), tf32r(rb.z), tf32r(rb.w));
    __syncthreads();

    float acc[2][4][4] = {};
    for (int kk = 0; kk < HH; kk += 8) {
        int cur = (kk >> 3) & 1;
        bool more = (kk + 8) < HH;
        if (more) {
            ra = *(const float4*)(Cb + (size_t)ar * HH + kk + 8 + ak);
            rw = *(const float4*)(w3 + kk + 8 + ak);
            if (t < 128) rb = *(const float4*)(Qb + (size_t)(t >> 1) * HH + kk + 8 + (t & 1) * 4);
        }
        uint32_t af[2][4], bf[4][2];
#pragma unroll
        for (int mi = 0; mi < 2; mi++) {
            int mb = m0w + mi * 16;
            af[mi][0] = __float_as_uint(As[cur][mb + r][c]);
            af[mi][1] = __float_as_uint(As[cur][mb + r + 8][c]);
            af[mi][2] = __float_as_uint(As[cur][mb + r][c + 4]);
            af[mi][3] = __float_as_uint(As[cur][mb + r + 8][c + 4]);
        }
#pragma unroll
        for (int ni = 0; ni < 4; ni++) {
            int nb = n0w + ni * 8 + r;
            bf[ni][0] = __float_as_uint(Bs[cur][nb][c]);
            bf[ni][1] = __float_as_uint(Bs[cur][nb][c + 4]);
        }
#pragma unroll
        for (int mi = 0; mi < 2; mi++)
#pragma unroll
            for (int ni = 0; ni < 4; ni++) mma8(acc[mi][ni], af[mi], bf[ni]);
        if (more) {
            int nxt = cur ^ 1;
            *(float4*)&As[nxt][ar][ak] =
                make_float4(tf32r(ra.x * rw.x), tf32r(ra.y * rw.y), tf32r(ra.z * rw.z), tf32r(ra.w * rw.w));
            if (t < 128)
                *(float4*)&Bs[nxt][t >> 1][(t & 1) * 4] =
                    make_float4(tf32r(rb.x), tf32r(rb.y), tf32r(rb.z), tf32r(rb.w));
        }
        __syncthreads();
    }
    float b0 = bias[0];
#pragma unroll
    for (int mi = 0; mi < 2; mi++)
#pragma unroll
        for (int ni = 0; ni < 4; ni++)
#pragma unroll
            for (int d = 0; d < 4; d++) {
                int i = i0 + m0w + mi * 16 + r + ((d >> 1) << 3);
                int j = j0 + n0w + ni * 8 + (c << 1) + (d & 1);
                g_S[((size_t)b * CL + i) * QL + j] =
                    acc[mi][ni][d] + g_cw1[b * CL + i] + g_qw2[b * QL + j] + b0;
            }
}

// ---------------------------------------------------------------------------
// K3: row softmax over j with Q_mask (warp per (b,i) row)
// ---------------------------------------------------------------------------
__global__ void k_rowsm(const int* __restrict__ qmask) {
    int warp = (blockIdx.x * blockDim.x + threadIdx.x) >> 5;
    int lane = threadIdx.x & 31;
    if (warp >= BB * CL) return;
    int b = warp / CL;
    const float* s = g_S + (size_t)warp * QL;
    const int* qm = qmask + b * QL;
    float v[4];
    float m = NEG;
#pragma unroll
    for (int q = 0; q < 4; q++) {
        int j = lane + 32 * q;
        v[q] = qm[j] ? s[j] : NEG;
        m = fmaxf(m, v[q]);
    }
#pragma unroll
    for (int off = 16; off; off >>= 1) m = fmaxf(m, __shfl_xor_sync(0xffffffffu, m, off));
    float sum = 0.f;
#pragma unroll
    for (int q = 0; q < 4; q++) { v[q] = expf(v[q] - m); sum += v[q]; }
#pragma unroll
    for (int off = 16; off; off >>= 1) sum += __shfl_xor_sync(0xffffffffu, sum, off);
    float inv = 1.f / sum;
#pragma unroll
    for (int q = 0; q < 4; q++) g_Srow[(size_t)warp * QL + lane + 32 * q] = v[q] * inv;
}

// ---------------------------------------------------------------------------
// K4: col softmax over i with C_mask. block (32,16)
// ---------------------------------------------------------------------------
__global__ void k_colsm(const int* __restrict__ cmask) {
    int b = blockIdx.y;
    int j = blockIdx.x * 32 + threadIdx.x;
    int ty = threadIdx.y;
    __shared__ float red[16][33];
    const int* cm = cmask + b * CL;
    const float* S = g_S + (size_t)b * CL * QL;
    float m = NEG;
    for (int i = ty; i < CL; i += 16) {
        float v = cm[i] ? S[(size_t)i * QL + j] : NEG;
        m = fmaxf(m, v);
    }
    red[ty][threadIdx.x] = m;
    __syncthreads();
    m = NEG;
#pragma unroll
    for (int y = 0; y < 16; y++) m = fmaxf(m, red[y][threadIdx.x]);
    __syncthreads();
    float s = 0.f;
    for (int i = ty; i < CL; i += 16) {
        float v = cm[i] ? S[(size_t)i * QL + j] : NEG;
        s += expf(v - m);
    }
    red[ty][threadIdx.x] = s;
    __syncthreads();
    s = 0.f;
#pragma unroll
    for (int y = 0; y < 16; y++) s += red[y][threadIdx.x];
    float inv = 1.f / s;
    float* Sc = g_Scol + (size_t)b * CL * QL;
    for (int i = ty; i < CL; i += 16) {
        float v = cm[i] ? S[(size_t)i * QL + j] : NEG;
        Sc[(size_t)i * QL + j] = expf(v - m) * inv;
    }
}

// ---------------------------------------------------------------------------
// K5: T[b,j,h] = sum_i Scol[b,i,j] * C[b,i,h]  via tf32 MMA
// block tile 128(j) x 64(h), K = i (1024). A:[k][m], B:[k][n]
// ---------------------------------------------------------------------------
__global__ __launch_bounds__(256) void k_tgemm(const float* __restrict__ C) {
    __shared__ float Ss[2][8][136];
    __shared__ float Cs[2][8][72];
    int b = blockIdx.z, h0 = blockIdx.y * 64;
    int t = threadIdx.x, lane = t & 31, wid = t >> 5;
    int m0w = (wid & 3) * 32, n0w = (wid >> 2) * 32;
    int r = lane >> 2, c = lane & 3;
    const float* Sc = g_Scol + (size_t)b * CL * QL;
    const float* Cb = C + (size_t)b * CL * HH;
    int sk = t >> 5, sm = (t & 31) * 4;

    float4 ra, rb;
    ra = *(const float4*)(Sc + (size_t)sk * QL + sm);
    if (t < 128) rb = *(const float4*)(Cb + (size_t)(t >> 4) * HH + h0 + (t & 15) * 4);
    *(float4*)&Ss[0][sk][sm] = make_float4(tf32r(ra.x), tf32r(ra.y), tf32r(ra.z), tf32r(ra.w));
    if (t < 128)
        *(float4*)&Cs[0][t >> 4][(t & 15) * 4] =
            make_float4(tf32r(rb.x), tf32r(rb.y), tf32r(rb.z), tf32r(rb.w));
    __syncthreads();

    float acc[2][4][4] = {};
    for (int kk = 0; kk < CL; kk += 8) {
        int cur = (kk >> 3) & 1;
        bool more = (kk + 8) < CL;
        if (more) {
            ra = *(const float4*)(Sc + (size_t)(kk + 8 + sk) * QL + sm);
            if (t < 128)
                rb = *(const float4*)(Cb + (size_t)(kk + 8 + (t >> 4)) * HH + h0 + (t & 15) * 4);
        }
        uint32_t af[2][4], bf[4][2];
#pragma unroll
        for (int mi = 0; mi < 2; mi++) {
            int mb = m0w + mi * 16;
            af[mi][0] = __float_as_uint(Ss[cur][c][mb + r]);
            af[mi][1] = __float_as_uint(Ss[cur][c][mb + r + 8]);
            af[mi][2] = __float_as_uint(Ss[cur][c + 4][mb + r]);
            af[mi][3] = __float_as_uint(Ss[cur][c + 4][mb + r + 8]);
        }
#pragma unroll
        for (int ni = 0; ni < 4; ni++) {
            int nb = n0w + ni * 8 + r;
            bf[ni][0] = __float_as_uint(Cs[cur][c][nb]);
            bf[ni][1] = __float_as_uint(Cs[cur][c + 4][nb]);
        }
#pragma unroll
        for (int mi = 0; mi < 2; mi++)
#pragma unroll
            for (int ni = 0; ni < 4; ni++) mma8(acc[mi][ni], af[mi], bf[ni]);
        if (more) {
            int nxt = cur ^ 1;
            *(float4*)&Ss[nxt][sk][sm] =
                make_float4(tf32r(ra.x), tf32r(ra.y), tf32r(ra.z), tf32r(ra.w));
            if (t < 128)
                *(float4*)&Cs[nxt][t >> 4][(t & 15) * 4] =
                    make_float4(tf32r(rb.x), tf32r(rb.y), tf32r(rb.z), tf32r(rb.w));
        }
        __syncthreads();
    }
#pragma unroll
    for (int mi = 0; mi < 2; mi++)
#pragma unroll
        for (int ni = 0; ni < 4; ni++)
#pragma unroll
            for (int d = 0; d < 4; d++) {
                int j = m0w + mi * 16 + r + ((d >> 1) << 3);
                int h = h0 + n0w + ni * 8 + (c << 1) + (d & 1);
                g_T[((size_t)b * QL + j) * HH + h] = acc[mi][ni][d];
            }
}

// ---------------------------------------------------------------------------
// K6: fused A = Srow@Q and Bm = Srow@T (K=128), writes concat output
// block tile 128(i) x 64(h). A:[m][k], BQ/BT:[k][n]
// ---------------------------------------------------------------------------
__global__ __launch_bounds__(256) void k_out(const float* __restrict__ C,
                                             const float* __restrict__ Q,
                                             float* __restrict__ out) {
    __shared__ float As[2][128][APAD];
    __shared__ float Qs[2][8][72];
    __shared__ float Ts[2][8][72];
    int b = blockIdx.z, i0 = blockIdx.x * 128, h0 = blockIdx.y * 64;
    int t = threadIdx.x, lane = t & 31, wid = t >> 5;
    int m0w = (wid & 3) * 32, n0w = (wid >> 2) * 32;
    int r = lane >> 2, c = lane & 3;
    const float* Sr = g_Srow + ((size_t)b * CL + i0) * QL;
    const float* Qb = Q + (size_t)b * QL * HH;
    const float* Tb = g_T + (size_t)b * QL * HH;
    int ar = t >> 1, ak = (t & 1) * 4;
    int t2 = t & 127, bk = t2 >> 4, bn = (t2 & 15) * 4;

    float4 ra, rb;
    ra = *(const float4*)(Sr + (size_t)ar * QL + ak);
    rb = (t < 128) ? *(const float4*)(Qb + (size_t)bk * HH + h0 + bn)
                   : *(const float4*)(Tb + (size_t)bk * HH + h0 + bn);
    *(float4*)&As[0][ar][ak] = make_float4(tf32r(ra.x), tf32r(ra.y), tf32r(ra.z), tf32r(ra.w));
    if (t < 128)
        *(float4*)&Qs[0][bk][bn] = make_float4(tf32r(rb.x), tf32r(rb.y), tf32r(rb.z), tf32r(rb.w));
    else
        *(float4*)&Ts[0][bk][bn] = make_float4(tf32r(rb.x), tf32r(rb.y), tf32r(rb.z), tf32r(rb.w));
    __syncthreads();

    float accA[2][4][4] = {}, accB[2][4][4] = {};
    for (int kk = 0; kk < QL; kk += 8) {
        int cur = (kk >> 3) & 1;
        bool more = (kk + 8) < QL;
        if (more) {
            ra = *(const float4*)(Sr + (size_t)ar * QL + kk + 8 + ak);
            rb = (t < 128) ? *(const float4*)(Qb + (size_t)(kk + 8 + bk) * HH + h0 + bn)
                           : *(const float4*)(Tb + (size_t)(kk + 8 + bk) * HH + h0 + bn);
        }
        uint32_t af[2][4], bq[4][2], bt[4][2];
#pragma unroll
        for (int mi = 0; mi < 2; mi++) {
            int mb = m0w + mi * 16;
            af[mi][0] = __float_as_uint(As[cur][mb + r][c]);
            af[mi][1] = __float_as_uint(As[cur][mb + r + 8][c]);
            af[mi][2] = __float_as_uint(As[cur][mb + r][c + 4]);
            af[mi][3] = __float_as_uint(As[cur][mb + r + 8][c + 4]);
        }
#pragma unroll
        for (int ni = 0; ni < 4; ni++) {
            int nb = n0w + ni * 8 + r;
            bq[ni][0] = __float_as_uint(Qs[cur][c][nb]);
            bq[ni][1] = __float_as_uint(Qs[cur][c + 4][nb]);
            bt[ni][0] = __float_as_uint(Ts[cur][c][nb]);
            bt[ni][1] = __float_as_uint(Ts[cur][c + 4][nb]);
        }
#pragma unroll
        for (int mi = 0; mi < 2; mi++)
#pragma unroll
            for (int ni = 0; ni < 4; ni++) {
                mma8(accA[mi][ni], af[mi], bq[ni]);
                mma8(accB[mi][ni], af[mi], bt[ni]);
            }
        if (more) {
            int nxt = cur ^ 1;
            *(float4*)&As[nxt][ar][ak] =
                make_float4(tf32r(ra.x), tf32r(ra.y), tf32r(ra.z), tf32r(ra.w));
            if (t < 128)
                *(float4*)&Qs[nxt][bk][bn] =
                    make_float4(tf32r(rb.x), tf32r(rb.y), tf32r(rb.z), tf32r(rb.w));
            else
                *(float4*)&Ts[nxt][bk][bn] =
                    make_float4(tf32r(rb.x), tf32r(rb.y), tf32r(rb.z), tf32r(rb.w));
        }
        __syncthreads();
    }
    const float* Cb = C + (size_t)b * CL * HH;
#pragma unroll
    for (int mi = 0; mi < 2; mi++)
#pragma unroll
        for (int ni = 0; ni < 4; ni++)
#pragma unroll
            for (int d = 0; d < 4; d++) {
                int i = i0 + m0w + mi * 16 + r + ((d >> 1) << 3);
                int h = h0 + n0w + ni * 8 + (c << 1) + (d & 1);
                float cv = Cb[(size_t)i * HH + h];
                float a = accA[mi][ni][d];
                float bm = accB[mi][ni][d];
                float* ob = out + ((size_t)b * CL + i) * (4 * HH) + h;
                ob[0] = cv;
                ob[HH] = a;
                ob[2 * HH] = cv * a;
                ob[3 * HH] = cv * bm;
            }
}

// ---------------------------------------------------------------------------
extern "C" void kernel_launch(void* const* d_in, const int* in_sizes, int n_in,
                              void* d_out, int out_size) {
    const float* C = (const float*)d_in[0];
    const float* Q = (const float*)d_in[1];
    const int* cmask = (const int*)d_in[2];
    const int* qmask = (const int*)d_in[3];
    const float* w = (const float*)d_in[4];
    const float* bias = (const float*)d_in[5];
    float* out = (float*)d_out;

    k_dots<<<4608, 256>>>(C, Q, w);
    k_sgemm<<<dim3(8, 2, 32), 256>>>(C, Q, w, bias);
    k_rowsm<<<4096, 256>>>(qmask);
    k_colsm<<<dim3(QL / 32, BB), dim3(32, 16)>>>(cmask);
    k_tgemm<<<dim3(1, 8, 32), 256>>>(C);
    k_out<<<dim3(8, 8, 32), 256>>>(C, Q, out);
}

// round 6
// speedup vs baseline: 2.0031x; 1.4938x over previous
#include <cuda_runtime.h>
#include <cstdint>

#define BB 32
#define CL 1024
#define QL 128
#define HH 512
#define NEG (-1e30f)

// ---- scratch (device globals; no allocations allowed) ----
__device__ float g_cw1[BB * CL];
__device__ float g_qw2[BB * QL];
__device__ float g_S[(size_t)BB * CL * QL];
__device__ float g_Srow[(size_t)BB * CL * QL];
__device__ float g_Scol[(size_t)BB * CL * QL];
__device__ float g_T[(size_t)BB * QL * HH];

__device__ __forceinline__ float tf32r(float x) {
    uint32_t u;
    asm("cvt.rna.tf32.f32 %0, %1;\n" : "=r"(u) : "f"(x));
    return __uint_as_float(u);
}
__device__ __forceinline__ float4 tf4(float4 v) {
    return make_float4(tf32r(v.x), tf32r(v.y), tf32r(v.z), tf32r(v.w));
}

__device__ __forceinline__ void mma8(float* d, const uint32_t* a, const uint32_t* b) {
    asm volatile(
        "mma.sync.aligned.m16n8k8.row.col.f32.tf32.tf32.f32 "
        "{%0,%1,%2,%3},{%4,%5,%6,%7},{%8,%9},{%0,%1,%2,%3};\n"
        : "+f"(d[0]), "+f"(d[1]), "+f"(d[2]), "+f"(d[3])
        : "r"(a[0]), "r"(a[1]), "r"(a[2]), "r"(a[3]), "r"(b[0]), "r"(b[1]));
}

// ---------------------------------------------------------------------------
// K1: cw1[b,i] = C[b,i]·w1 ; qw2[b,j] = Q[b,j]·w2   (warp per row)
// ---------------------------------------------------------------------------
__global__ void k_dots(const float* __restrict__ C, const float* __restrict__ Q,
                       const float* __restrict__ w) {
    int warp = (blockIdx.x * blockDim.x + threadIdx.x) >> 5;
    int lane = threadIdx.x & 31;
    const int nC = BB * CL;
    if (warp >= nC + BB * QL) return;
    const float* row;
    const float* wp;
    float* out;
    if (warp < nC) {
        row = C + (size_t)warp * HH; wp = w;      out = g_cw1 + warp;
    } else {
        int r = warp - nC;
        row = Q + (size_t)r * HH;    wp = w + HH; out = g_qw2 + r;
    }
    const float4* r4 = (const float4*)row;
    const float4* w4 = (const float4*)wp;
    float acc = 0.f;
#pragma unroll
    for (int q = 0; q < 4; q++) {
        float4 v = r4[lane + 32 * q];
        float4 ww = w4[lane + 32 * q];
        acc += v.x * ww.x + v.y * ww.y + v.z * ww.z + v.w * ww.w;
    }
#pragma unroll
    for (int off = 16; off; off >>= 1) acc += __shfl_xor_sync(0xffffffffu, acc, off);
    if (lane == 0) *out = acc;
}

// ---------------------------------------------------------------------------
// K2: S = (C*w3)@Q^T + cw1 + qw2 + b  via tf32 MMA
// tile 128(i) x 128(j=all QL), Kc=16 double-buffered. A:[m][k], B:[n][k]
// warps 4(m) x 2(n), warp tile 32 x 64
// ---------------------------------------------------------------------------
__global__ __launch_bounds__(256) void k_sgemm(const float* __restrict__ C,
                                               const float* __restrict__ Q,
                                               const float* __restrict__ w,
                                               const float* __restrict__ bias) {
    __shared__ float As[2][128][20];
    __shared__ float Bs[2][128][20];
    int b = blockIdx.z, i0 = blockIdx.x * 128;
    int t = threadIdx.x, lane = t & 31, wid = t >> 5;
    int m0w = (wid & 3) * 32, n0w = (wid >> 2) * 64;
    int r = lane >> 2, c = lane & 3;
    const float* w3 = w + 2 * HH;
    const float* Cb = C + ((size_t)b * CL + i0) * HH;
    const float* Qb = Q + (size_t)b * QL * HH;
    int lr = t >> 1, lk = (t & 1) * 8;

    float4 a1, a2, w1v, w2v, q1, q2;
    a1 = *(const float4*)(Cb + (size_t)lr * HH + lk);
    a2 = *(const float4*)(Cb + (size_t)lr * HH + lk + 4);
    w1v = *(const float4*)(w3 + lk);
    w2v = *(const float4*)(w3 + lk + 4);
    q1 = *(const float4*)(Qb + (size_t)lr * HH + lk);
    q2 = *(const float4*)(Qb + (size_t)lr * HH + lk + 4);
    *(float4*)&As[0][lr][lk] = make_float4(tf32r(a1.x * w1v.x), tf32r(a1.y * w1v.y),
                                           tf32r(a1.z * w1v.z), tf32r(a1.w * w1v.w));
    *(float4*)&As[0][lr][lk + 4] = make_float4(tf32r(a2.x * w2v.x), tf32r(a2.y * w2v.y),
                                               tf32r(a2.z * w2v.z), tf32r(a2.w * w2v.w));
    *(float4*)&Bs[0][lr][lk] = tf4(q1);
    *(float4*)&Bs[0][lr][lk + 4] = tf4(q2);
    __syncthreads();

    float acc[2][8][4] = {};
    for (int kk = 0; kk < HH; kk += 16) {
        int cur = (kk >> 4) & 1;
        bool more = (kk + 16) < HH;
        if (more) {
            a1 = *(const float4*)(Cb + (size_t)lr * HH + kk + 16 + lk);
            a2 = *(const float4*)(Cb + (size_t)lr * HH + kk + 16 + lk + 4);
            w1v = *(const float4*)(w3 + kk + 16 + lk);
            w2v = *(const float4*)(w3 + kk + 16 + lk + 4);
            q1 = *(const float4*)(Qb + (size_t)lr * HH + kk + 16 + lk);
            q2 = *(const float4*)(Qb + (size_t)lr * HH + kk + 16 + lk + 4);
        }
#pragma unroll
        for (int h = 0; h < 2; h++) {
            int ck = h * 8 + c;
            uint32_t af[2][4], bf[8][2];
#pragma unroll
            for (int mi = 0; mi < 2; mi++) {
                int mb = m0w + mi * 16;
                af[mi][0] = __float_as_uint(As[cur][mb + r][ck]);
                af[mi][1] = __float_as_uint(As[cur][mb + r + 8][ck]);
                af[mi][2] = __float_as_uint(As[cur][mb + r][ck + 4]);
                af[mi][3] = __float_as_uint(As[cur][mb + r + 8][ck + 4]);
            }
#pragma unroll
            for (int ni = 0; ni < 8; ni++) {
                int nb = n0w + ni * 8 + r;
                bf[ni][0] = __float_as_uint(Bs[cur][nb][ck]);
                bf[ni][1] = __float_as_uint(Bs[cur][nb][ck + 4]);
            }
#pragma unroll
            for (int mi = 0; mi < 2; mi++)
#pragma unroll
                for (int ni = 0; ni < 8; ni++) mma8(acc[mi][ni], af[mi], bf[ni]);
        }
        if (more) {
            int nxt = cur ^ 1;
            *(float4*)&As[nxt][lr][lk] = make_float4(tf32r(a1.x * w1v.x), tf32r(a1.y * w1v.y),
                                                     tf32r(a1.z * w1v.z), tf32r(a1.w * w1v.w));
            *(float4*)&As[nxt][lr][lk + 4] = make_float4(tf32r(a2.x * w2v.x), tf32r(a2.y * w2v.y),
                                                         tf32r(a2.z * w2v.z), tf32r(a2.w * w2v.w));
            *(float4*)&Bs[nxt][lr][lk] = tf4(q1);
            *(float4*)&Bs[nxt][lr][lk + 4] = tf4(q2);
        }
        __syncthreads();
    }
    float b0 = bias[0];
#pragma unroll
    for (int mi = 0; mi < 2; mi++)
#pragma unroll
        for (int dh = 0; dh < 2; dh++) {
            int i = i0 + m0w + mi * 16 + r + dh * 8;
            float cw = g_cw1[b * CL + i] + b0;
            float* So = g_S + ((size_t)b * CL + i) * QL;
#pragma unroll
            for (int ni = 0; ni < 8; ni++) {
                int j = n0w + ni * 8 + (c << 1);
                float2 qv = *(const float2*)(g_qw2 + b * QL + j);
                float2 o;
                o.x = acc[mi][ni][dh * 2 + 0] + cw + qv.x;
                o.y = acc[mi][ni][dh * 2 + 1] + cw + qv.y;
                *(float2*)(So + j) = o;
            }
        }
}

// ---------------------------------------------------------------------------
// K3: row softmax over j with Q_mask (warp per (b,i) row)
// ---------------------------------------------------------------------------
__global__ void k_rowsm(const int* __restrict__ qmask) {
    int warp = (blockIdx.x * blockDim.x + threadIdx.x) >> 5;
    int lane = threadIdx.x & 31;
    if (warp >= BB * CL) return;
    int b = warp / CL;
    const float* s = g_S + (size_t)warp * QL;
    const int* qm = qmask + b * QL;
    float v[4];
    float m = NEG;
#pragma unroll
    for (int q = 0; q < 4; q++) {
        int j = lane + 32 * q;
        v[q] = qm[j] ? s[j] : NEG;
        m = fmaxf(m, v[q]);
    }
#pragma unroll
    for (int off = 16; off; off >>= 1) m = fmaxf(m, __shfl_xor_sync(0xffffffffu, m, off));
    float sum = 0.f;
#pragma unroll
    for (int q = 0; q < 4; q++) { v[q] = __expf(v[q] - m); sum += v[q]; }
#pragma unroll
    for (int off = 16; off; off >>= 1) sum += __shfl_xor_sync(0xffffffffu, sum, off);
    float inv = 1.f / sum;
#pragma unroll
    for (int q = 0; q < 4; q++) g_Srow[(size_t)warp * QL + lane + 32 * q] = v[q] * inv;
}

// ---------------------------------------------------------------------------
// K4: col softmax over i with C_mask. block (32,16)
// ---------------------------------------------------------------------------
__global__ void k_colsm(const int* __restrict__ cmask) {
    int b = blockIdx.y;
    int j = blockIdx.x * 32 + threadIdx.x;
    int ty = threadIdx.y;
    __shared__ float red[16][33];
    const int* cm = cmask + b * CL;
    const float* S = g_S + (size_t)b * CL * QL;
    float m = NEG;
    for (int i = ty; i < CL; i += 16) {
        float v = cm[i] ? S[(size_t)i * QL + j] : NEG;
        m = fmaxf(m, v);
    }
    red[ty][threadIdx.x] = m;
    __syncthreads();
    m = NEG;
#pragma unroll
    for (int y = 0; y < 16; y++) m = fmaxf(m, red[y][threadIdx.x]);
    __syncthreads();
    float s = 0.f;
    for (int i = ty; i < CL; i += 16) {
        float v = cm[i] ? S[(size_t)i * QL + j] : NEG;
        s += __expf(v - m);
    }
    red[ty][threadIdx.x] = s;
    __syncthreads();
    s = 0.f;
#pragma unroll
    for (int y = 0; y < 16; y++) s += red[y][threadIdx.x];
    float inv = 1.f / s;
    float* Sc = g_Scol + (size_t)b * CL * QL;
    for (int i = ty; i < CL; i += 16) {
        float v = cm[i] ? S[(size_t)i * QL + j] : NEG;
        Sc[(size_t)i * QL + j] = __expf(v - m) * inv;
    }
}

// ---------------------------------------------------------------------------
// K5: T[b,j,h] = sum_i Scol[b,i,j] * C[b,i,h]  via tf32 MMA
// tile 128(j) x 64(h), K=1024, Kc=16. A:[k][m], B:[k][n]. warps 4x2, 32x32
// ---------------------------------------------------------------------------
__global__ __launch_bounds__(256) void k_tgemm(const float* __restrict__ C) {
    __shared__ float Ss[2][16][132];
    __shared__ float Cs[2][16][68];
    int b = blockIdx.z, h0 = blockIdx.y * 64;
    int t = threadIdx.x, lane = t & 31, wid = t >> 5;
    int m0w = (wid & 3) * 32, n0w = (wid >> 2) * 32;
    int r = lane >> 2, c = lane & 3;
    const float* Sc = g_Scol + (size_t)b * CL * QL;
    const float* Cb = C + (size_t)b * CL * HH;
    int si0 = t >> 5, sj = (t & 31) * 4;     // 2 rows per thread via +8
    int ci = t >> 4, ch = (t & 15) * 4;

    float4 s1, s2, cv;
    s1 = *(const float4*)(Sc + (size_t)si0 * QL + sj);
    s2 = *(const float4*)(Sc + (size_t)(si0 + 8) * QL + sj);
    cv = *(const float4*)(Cb + (size_t)ci * HH + h0 + ch);
    *(float4*)&Ss[0][si0][sj] = tf4(s1);
    *(float4*)&Ss[0][si0 + 8][sj] = tf4(s2);
    *(float4*)&Cs[0][ci][ch] = tf4(cv);
    __syncthreads();

    float acc[2][4][4] = {};
    for (int kk = 0; kk < CL; kk += 16) {
        int cur = (kk >> 4) & 1;
        bool more = (kk + 16) < CL;
        if (more) {
            s1 = *(const float4*)(Sc + (size_t)(kk + 16 + si0) * QL + sj);
            s2 = *(const float4*)(Sc + (size_t)(kk + 16 + si0 + 8) * QL + sj);
            cv = *(const float4*)(Cb + (size_t)(kk + 16 + ci) * HH + h0 + ch);
        }
#pragma unroll
        for (int h = 0; h < 2; h++) {
            int ck = h * 8 + c;
            uint32_t af[2][4], bf[4][2];
#pragma unroll
            for (int mi = 0; mi < 2; mi++) {
                int mb = m0w + mi * 16;
                af[mi][0] = __float_as_uint(Ss[cur][ck][mb + r]);
                af[mi][1] = __float_as_uint(Ss[cur][ck][mb + r + 8]);
                af[mi][2] = __float_as_uint(Ss[cur][ck + 4][mb + r]);
                af[mi][3] = __float_as_uint(Ss[cur][ck + 4][mb + r + 8]);
            }
#pragma unroll
            for (int ni = 0; ni < 4; ni++) {
                int nb = n0w + ni * 8 + r;
                bf[ni][0] = __float_as_uint(Cs[cur][ck][nb]);
                bf[ni][1] = __float_as_uint(Cs[cur][ck + 4][nb]);
            }
#pragma unroll
            for (int mi = 0; mi < 2; mi++)
#pragma unroll
                for (int ni = 0; ni < 4; ni++) mma8(acc[mi][ni], af[mi], bf[ni]);
        }
        if (more) {
            int nxt = cur ^ 1;
            *(float4*)&Ss[nxt][si0][sj] = tf4(s1);
            *(float4*)&Ss[nxt][si0 + 8][sj] = tf4(s2);
            *(float4*)&Cs[nxt][ci][ch] = tf4(cv);
        }
        __syncthreads();
    }
#pragma unroll
    for (int mi = 0; mi < 2; mi++)
#pragma unroll
        for (int dh = 0; dh < 2; dh++) {
            int j = m0w + mi * 16 + r + dh * 8;
            float* To = g_T + ((size_t)b * QL + j) * HH + h0;
#pragma unroll
            for (int ni = 0; ni < 4; ni++) {
                int h = n0w + ni * 8 + (c << 1);
                *(float2*)(To + h) =
                    make_float2(acc[mi][ni][dh * 2 + 0], acc[mi][ni][dh * 2 + 1]);
            }
        }
}

// ---------------------------------------------------------------------------
// K6: fused A = Srow@Q and Bm = Srow@T (K=128), writes concat output
// tile 128(i) x 64(h). A:[m][k], BQ/BT:[k][n]. warps 4x2, 32x32, Kc=16
// ---------------------------------------------------------------------------
__global__ __launch_bounds__(256) void k_out(const float* __restrict__ C,
                                             const float* __restrict__ Q,
                                             float* __restrict__ out) {
    __shared__ float As[2][128][20];
    __shared__ float Qs[2][16][68];
    __shared__ float Ts[2][16][68];
    int b = blockIdx.z, i0 = blockIdx.x * 128, h0 = blockIdx.y * 64;
    int t = threadIdx.x, lane = t & 31, wid = t >> 5;
    int m0w = (wid & 3) * 32, n0w = (wid >> 2) * 32;
    int r = lane >> 2, c = lane & 3;
    const float* Sr = g_Srow + ((size_t)b * CL + i0) * QL;
    const float* Qb = Q + (size_t)b * QL * HH;
    const float* Tb = g_T + (size_t)b * QL * HH;
    int lr = t >> 1, lk = (t & 1) * 8;
    int ci = t >> 4, ch = (t & 15) * 4;

    float4 a1, a2, qv, tv;
    a1 = *(const float4*)(Sr + (size_t)lr * QL + lk);
    a2 = *(const float4*)(Sr + (size_t)lr * QL + lk + 4);
    qv = *(const float4*)(Qb + (size_t)ci * HH + h0 + ch);
    tv = *(const float4*)(Tb + (size_t)ci * HH + h0 + ch);
    *(float4*)&As[0][lr][lk] = tf4(a1);
    *(float4*)&As[0][lr][lk + 4] = tf4(a2);
    *(float4*)&Qs[0][ci][ch] = tf4(qv);
    *(float4*)&Ts[0][ci][ch] = tf4(tv);
    __syncthreads();

    float accA[2][4][4] = {}, accB[2][4][4] = {};
    for (int kk = 0; kk < QL; kk += 16) {
        int cur = (kk >> 4) & 1;
        bool more = (kk + 16) < QL;
        if (more) {
            a1 = *(const float4*)(Sr + (size_t)lr * QL + kk + 16 + lk);
            a2 = *(const float4*)(Sr + (size_t)lr * QL + kk + 16 + lk + 4);
            qv = *(const float4*)(Qb + (size_t)(kk + 16 + ci) * HH + h0 + ch);
            tv = *(const float4*)(Tb + (size_t)(kk + 16 + ci) * HH + h0 + ch);
        }
#pragma unroll
        for (int h = 0; h < 2; h++) {
            int ck = h * 8 + c;
            uint32_t af[2][4], bq[4][2], bt[4][2];
#pragma unroll
            for (int mi = 0; mi < 2; mi++) {
                int mb = m0w + mi * 16;
                af[mi][0] = __float_as_uint(As[cur][mb + r][ck]);
                af[mi][1] = __float_as_uint(As[cur][mb + r + 8][ck]);
                af[mi][2] = __float_as_uint(As[cur][mb + r][ck + 4]);
                af[mi][3] = __float_as_uint(As[cur][mb + r + 8][ck + 4]);
            }
#pragma unroll
            for (int ni = 0; ni < 4; ni++) {
                int nb = n0w + ni * 8 + r;
                bq[ni][0] = __float_as_uint(Qs[cur][ck][nb]);
                bq[ni][1] = __float_as_uint(Qs[cur][ck + 4][nb]);
                bt[ni][0] = __float_as_uint(Ts[cur][ck][nb]);
                bt[ni][1] = __float_as_uint(Ts[cur][ck + 4][nb]);
            }
#pragma unroll
            for (int mi = 0; mi < 2; mi++)
#pragma unroll
                for (int ni = 0; ni < 4; ni++) {
                    mma8(accA[mi][ni], af[mi], bq[ni]);
                    mma8(accB[mi][ni], af[mi], bt[ni]);
                }
        }
        if (more) {
            int nxt = cur ^ 1;
            *(float4*)&As[nxt][lr][lk] = tf4(a1);
            *(float4*)&As[nxt][lr][lk + 4] = tf4(a2);
            *(float4*)&Qs[nxt][ci][ch] = tf4(qv);
            *(float4*)&Ts[nxt][ci][ch] = tf4(tv);
        }
        __syncthreads();
    }
    const float* Cb = C + (size_t)b * CL * HH;
#pragma unroll
    for (int mi = 0; mi < 2; mi++)
#pragma unroll
        for (int dh = 0; dh < 2; dh++) {
            int i = i0 + m0w + mi * 16 + r + dh * 8;
            const float* Crow = Cb + (size_t)i * HH;
            float* ob = out + ((size_t)b * CL + i) * (4 * HH);
#pragma unroll
            for (int ni = 0; ni < 4; ni++) {
                int h = h0 + n0w + ni * 8 + (c << 1);
                float2 cv = *(const float2*)(Crow + h);
                float2 av = make_float2(accA[mi][ni][dh * 2], accA[mi][ni][dh * 2 + 1]);
                float2 bv = make_float2(accB[mi][ni][dh * 2], accB[mi][ni][dh * 2 + 1]);
                *(float2*)(ob + h) = cv;
                *(float2*)(ob + HH + h) = av;
                *(float2*)(ob + 2 * HH + h) = make_float2(cv.x * av.x, cv.y * av.y);
                *(float2*)(ob + 3 * HH + h) = make_float2(cv.x * bv.x, cv.y * bv.y);
            }
        }
}

// ---------------------------------------------------------------------------
extern "C" void kernel_launch(void* const* d_in, const int* in_sizes, int n_in,
                              void* d_out, int out_size) {
    const float* C = (const float*)d_in[0];
    const float* Q = (const float*)d_in[1];
    const int* cmask = (const int*)d_in[2];
    const int* qmask = (const int*)d_in[3];
    const float* w = (const float*)d_in[4];
    const float* bias = (const float*)d_in[5];
    float* out = (float*)d_out;

    k_dots<<<4608, 256>>>(C, Q, w);
    k_sgemm<<<dim3(8, 1, 32), 256>>>(C, Q, w, bias);
    k_rowsm<<<4096, 256>>>(qmask);
    k_colsm<<<dim3(QL / 32, BB), dim3(32, 16)>>>(cmask);
    k_tgemm<<<dim3(1, 8, 32), 256>>>(C);
    k_out<<<dim3(8, 8, 32), 256>>>(C, Q, out);
}

// round 7
// speedup vs baseline: 2.0815x; 1.0392x over previous
#include <cuda_runtime.h>
#include <cstdint>

#define BB 32
#define CL 1024
#define QL 128
#define HH 512
#define NEG (-1e30f)

// ---- scratch (device globals; no allocations allowed) ----
__device__ float g_S[(size_t)BB * CL * QL];     // raw scores
__device__ float g_Srow[(size_t)BB * CL * QL];  // row softmax
__device__ float g_T[(size_t)BB * QL * HH];     // T = Scol^T @ C (scaled)
__device__ float g_cmax[BB * QL];               // col-softmax max per j
__device__ float g_cinv[BB * QL];               // 1 / col-softmax sum per j

__device__ __forceinline__ float tf32r(float x) {
    uint32_t u;
    asm("cvt.rna.tf32.f32 %0, %1;\n" : "=r"(u) : "f"(x));
    return __uint_as_float(u);
}
__device__ __forceinline__ float4 tf4(float4 v) {
    return make_float4(tf32r(v.x), tf32r(v.y), tf32r(v.z), tf32r(v.w));
}
__device__ __forceinline__ float dot4(float4 a, float4 b) {
    return a.x * b.x + a.y * b.y + a.z * b.z + a.w * b.w;
}

__device__ __forceinline__ void mma8(float* d, const uint32_t* a, const uint32_t* b) {
    asm volatile(
        "mma.sync.aligned.m16n8k8.row.col.f32.tf32.tf32.f32 "
        "{%0,%1,%2,%3},{%4,%5,%6,%7},{%8,%9},{%0,%1,%2,%3};\n"
        : "+f"(d[0]), "+f"(d[1]), "+f"(d[2]), "+f"(d[3])
        : "r"(a[0]), "r"(a[1]), "r"(a[2]), "r"(a[3]), "r"(b[0]), "r"(b[1]));
}

// ---------------------------------------------------------------------------
// K2: S = (C*w3)@Q^T + (C@w1)[i] + (Q@w2)[j] + b, fused row-softmax epilogue.
// tile 128(i) x 128(j=all QL), Kc=16 double-buffered. warps 4(m) x 2(n), 32x64.
// cw1/qw2 dots computed in the fill stage (C/Q rows already in registers).
// ---------------------------------------------------------------------------
__global__ __launch_bounds__(256) void k_sgemm(const float* __restrict__ C,
                                               const float* __restrict__ Q,
                                               const float* __restrict__ w,
                                               const float* __restrict__ bias,
                                               const int* __restrict__ qmask) {
    __shared__ float As[2][128][20];
    __shared__ float Bs[2][128][20];
    __shared__ float scw1[128], sqw2[128];
    __shared__ int sqm[128];
    __shared__ float pm[128][2], ps[128][2];

    int b = blockIdx.z, i0 = blockIdx.x * 128;
    int t = threadIdx.x, lane = t & 31, wid = t >> 5;
    int m0w = (wid & 3) * 32, n0w = (wid >> 2) * 64;
    int r = lane >> 2, c = lane & 3;
    const float* w1 = w;
    const float* w2 = w + HH;
    const float* w3 = w + 2 * HH;
    const float* Cb = C + ((size_t)b * CL + i0) * HH;
    const float* Qb = Q + (size_t)b * QL * HH;
    int lr = t >> 1, lk = (t & 1) * 8;

    if (t < 128) sqm[t] = qmask[b * QL + t];

    float cwacc = 0.f, qwacc = 0.f;
    float4 a1, a2, q1, q2, w3a, w3b;
    a1 = *(const float4*)(Cb + (size_t)lr * HH + lk);
    a2 = *(const float4*)(Cb + (size_t)lr * HH + lk + 4);
    q1 = *(const float4*)(Qb + (size_t)lr * HH + lk);
    q2 = *(const float4*)(Qb + (size_t)lr * HH + lk + 4);
    w3a = *(const float4*)(w3 + lk);
    w3b = *(const float4*)(w3 + lk + 4);
    cwacc += dot4(a1, *(const float4*)(w1 + lk)) + dot4(a2, *(const float4*)(w1 + lk + 4));
    qwacc += dot4(q1, *(const float4*)(w2 + lk)) + dot4(q2, *(const float4*)(w2 + lk + 4));
    *(float4*)&As[0][lr][lk] = make_float4(tf32r(a1.x * w3a.x), tf32r(a1.y * w3a.y),
                                           tf32r(a1.z * w3a.z), tf32r(a1.w * w3a.w));
    *(float4*)&As[0][lr][lk + 4] = make_float4(tf32r(a2.x * w3b.x), tf32r(a2.y * w3b.y),
                                               tf32r(a2.z * w3b.z), tf32r(a2.w * w3b.w));
    *(float4*)&Bs[0][lr][lk] = tf4(q1);
    *(float4*)&Bs[0][lr][lk + 4] = tf4(q2);
    __syncthreads();

    float acc[2][8][4] = {};
    for (int kk = 0; kk < HH; kk += 16) {
        int cur = (kk >> 4) & 1;
        bool more = (kk + 16) < HH;
        if (more) {
            int k2 = kk + 16;
            a1 = *(const float4*)(Cb + (size_t)lr * HH + k2 + lk);
            a2 = *(const float4*)(Cb + (size_t)lr * HH + k2 + lk + 4);
            q1 = *(const float4*)(Qb + (size_t)lr * HH + k2 + lk);
            q2 = *(const float4*)(Qb + (size_t)lr * HH + k2 + lk + 4);
            w3a = *(const float4*)(w3 + k2 + lk);
            w3b = *(const float4*)(w3 + k2 + lk + 4);
            cwacc += dot4(a1, *(const float4*)(w1 + k2 + lk)) +
                     dot4(a2, *(const float4*)(w1 + k2 + lk + 4));
            qwacc += dot4(q1, *(const float4*)(w2 + k2 + lk)) +
                     dot4(q2, *(const float4*)(w2 + k2 + lk + 4));
        }
#pragma unroll
        for (int h = 0; h < 2; h++) {
            int ck = h * 8 + c;
            uint32_t af[2][4], bf[8][2];
#pragma unroll
            for (int mi = 0; mi < 2; mi++) {
                int mb = m0w + mi * 16;
                af[mi][0] = __float_as_uint(As[cur][mb + r][ck]);
                af[mi][1] = __float_as_uint(As[cur][mb + r + 8][ck]);
                af[mi][2] = __float_as_uint(As[cur][mb + r][ck + 4]);
                af[mi][3] = __float_as_uint(As[cur][mb + r + 8][ck + 4]);
            }
#pragma unroll
            for (int ni = 0; ni < 8; ni++) {
                int nb = n0w + ni * 8 + r;
                bf[ni][0] = __float_as_uint(Bs[cur][nb][ck]);
                bf[ni][1] = __float_as_uint(Bs[cur][nb][ck + 4]);
            }
#pragma unroll
            for (int mi = 0; mi < 2; mi++)
#pragma unroll
                for (int ni = 0; ni < 8; ni++) mma8(acc[mi][ni], af[mi], bf[ni]);
        }
        if (more) {
            int nxt = cur ^ 1;
            *(float4*)&As[nxt][lr][lk] = make_float4(tf32r(a1.x * w3a.x), tf32r(a1.y * w3a.y),
                                                     tf32r(a1.z * w3a.z), tf32r(a1.w * w3a.w));
            *(float4*)&As[nxt][lr][lk + 4] = make_float4(tf32r(a2.x * w3b.x), tf32r(a2.y * w3b.y),
                                                         tf32r(a2.z * w3b.z), tf32r(a2.w * w3b.w));
            *(float4*)&Bs[nxt][lr][lk] = tf4(q1);
            *(float4*)&Bs[nxt][lr][lk + 4] = tf4(q2);
        }
        __syncthreads();
    }

    // finish fused dot-products: pair (t, t^1) covers the full K of row lr
    cwacc += __shfl_xor_sync(0xffffffffu, cwacc, 1);
    qwacc += __shfl_xor_sync(0xffffffffu, qwacc, 1);
    if ((t & 1) == 0) { scw1[lr] = cwacc; sqw2[lr] = qwacc; }
    __syncthreads();

    float b0 = bias[0];
    int nhalf = wid >> 2;
    // add cw1 + qw2 + b into acc (acc becomes raw S values)
    float qw[8][2];
#pragma unroll
    for (int ni = 0; ni < 8; ni++) {
        int j = n0w + ni * 8 + (c << 1);
        qw[ni][0] = sqw2[j];
        qw[ni][1] = sqw2[j + 1];
    }
#pragma unroll
    for (int mi = 0; mi < 2; mi++)
#pragma unroll
        for (int dh = 0; dh < 2; dh++) {
            float cw = scw1[m0w + mi * 16 + r + dh * 8] + b0;
#pragma unroll
            for (int ni = 0; ni < 8; ni++) {
                acc[mi][ni][dh * 2 + 0] += cw + qw[ni][0];
                acc[mi][ni][dh * 2 + 1] += cw + qw[ni][1];
            }
        }
    // row max (masked)
#pragma unroll
    for (int mi = 0; mi < 2; mi++)
#pragma unroll
        for (int dh = 0; dh < 2; dh++) {
            int il = m0w + mi * 16 + r + dh * 8;
            float mx = NEG;
#pragma unroll
            for (int ni = 0; ni < 8; ni++) {
                int j = n0w + ni * 8 + (c << 1);
                mx = fmaxf(mx, sqm[j] ? acc[mi][ni][dh * 2] : NEG);
                mx = fmaxf(mx, sqm[j + 1] ? acc[mi][ni][dh * 2 + 1] : NEG);
            }
            mx = fmaxf(mx, __shfl_xor_sync(0xffffffffu, mx, 1));
            mx = fmaxf(mx, __shfl_xor_sync(0xffffffffu, mx, 2));
            if (c == 0) pm[il][nhalf] = mx;
        }
    __syncthreads();
    // row sum
    float m2[2][2];
#pragma unroll
    for (int mi = 0; mi < 2; mi++)
#pragma unroll
        for (int dh = 0; dh < 2; dh++) {
            int il = m0w + mi * 16 + r + dh * 8;
            float m = fmaxf(pm[il][0], pm[il][1]);
            m2[mi][dh] = m;
            float sum = 0.f;
#pragma unroll
            for (int ni = 0; ni < 8; ni++) {
                int j = n0w + ni * 8 + (c << 1);
                float x0 = sqm[j] ? acc[mi][ni][dh * 2] : NEG;
                float x1 = sqm[j + 1] ? acc[mi][ni][dh * 2 + 1] : NEG;
                sum += __expf(x0 - m) + __expf(x1 - m);
            }
            sum += __shfl_xor_sync(0xffffffffu, sum, 1);
            sum += __shfl_xor_sync(0xffffffffu, sum, 2);
            if (c == 0) ps[il][nhalf] = sum;
        }
    __syncthreads();
    // write raw S and Srow
#pragma unroll
    for (int mi = 0; mi < 2; mi++)
#pragma unroll
        for (int dh = 0; dh < 2; dh++) {
            int il = m0w + mi * 16 + r + dh * 8;
            int i = i0 + il;
            float m = m2[mi][dh];
            float inv = 1.f / (ps[il][0] + ps[il][1]);
            float* So = g_S + ((size_t)b * CL + i) * QL;
            float* Sr = g_Srow + ((size_t)b * CL + i) * QL;
#pragma unroll
            for (int ni = 0; ni < 8; ni++) {
                int j = n0w + ni * 8 + (c << 1);
                float v0 = acc[mi][ni][dh * 2], v1 = acc[mi][ni][dh * 2 + 1];
                *(float2*)(So + j) = make_float2(v0, v1);
                float e0 = __expf((sqm[j] ? v0 : NEG) - m) * inv;
                float e1 = __expf((sqm[j + 1] ? v1 : NEG) - m) * inv;
                *(float2*)(Sr + j) = make_float2(e0, e1);
            }
        }
}

// ---------------------------------------------------------------------------
// K4: col-softmax REDUCTION only (online m,s per column j). Single S pass.
// ---------------------------------------------------------------------------
__global__ void k_colsm(const int* __restrict__ cmask) {
    __shared__ float rm[16][33], rs[16][33];
    int b = blockIdx.y, tx = threadIdx.x, ty = threadIdx.y;
    int j = blockIdx.x * 32 + tx;
    const int* cm = cmask + b * CL;
    const float* S = g_S + (size_t)b * CL * QL;
    float m = NEG, s = 0.f;
    for (int i = ty; i < CL; i += 16) {
        float v = cm[i] ? S[(size_t)i * QL + j] : NEG;
        if (v > m) {
            s = s * __expf(m - v) + 1.f;
            m = v;
        } else {
            s += __expf(v - m);
        }
    }
    rm[ty][tx] = m;
    rs[ty][tx] = s;
    __syncthreads();
    if (ty == 0) {
        float M = NEG;
#pragma unroll
        for (int y = 0; y < 16; y++) M = fmaxf(M, rm[y][tx]);
        float S_ = 0.f;
#pragma unroll
        for (int y = 0; y < 16; y++) S_ += rs[y][tx] * __expf(rm[y][tx] - M);
        g_cmax[b * QL + j] = M;
        g_cinv[b * QL + j] = 1.f / S_;
    }
}

// ---------------------------------------------------------------------------
// K5: T[j,h] = (1/s[j]) * sum_i [cm[i] ? exp(S[i,j]-m[j]) : 0] * C[i,h]
// exp computed inline in the fill stage; scale in epilogue. g_Scol eliminated.
// tile 128(j) x 128(h), K=1024, Kc=16. warps 4x2, warp 32x64.
// ---------------------------------------------------------------------------
__global__ __launch_bounds__(256) void k_tgemm(const float* __restrict__ C,
                                               const int* __restrict__ cmask) {
    __shared__ float Ss[2][16][136];
    __shared__ float Cs[2][16][136];
    __shared__ float smax[128], sinv[128];
    int b = blockIdx.z, h0 = blockIdx.y * 128;
    int t = threadIdx.x, lane = t & 31, wid = t >> 5;
    int m0w = (wid & 3) * 32, n0w = (wid >> 2) * 64;
    int r = lane >> 2, c = lane & 3;
    const float* Sb = g_S + (size_t)b * CL * QL;
    const float* Cb = C + (size_t)b * CL * HH;
    const int* cm = cmask + b * CL;
    int si = t >> 5, sj = (t & 31) * 4;   // A fill: rows si, si+8; cols sj..sj+3
    int ci = t >> 4, ch = (t & 15) * 8;   // B fill: row ci; cols ch..ch+7

    if (t < 128) {
        smax[t] = g_cmax[b * QL + t];
        sinv[t] = g_cinv[b * QL + t];
    }
    __syncthreads();
    float4 msj = *(const float4*)(smax + sj);

    float4 s1, s2, c1, c2;
    int cm0, cm1;
    s1 = *(const float4*)(Sb + (size_t)si * QL + sj);
    s2 = *(const float4*)(Sb + (size_t)(si + 8) * QL + sj);
    c1 = *(const float4*)(Cb + (size_t)ci * HH + h0 + ch);
    c2 = *(const float4*)(Cb + (size_t)ci * HH + h0 + ch + 4);
    cm0 = cm[si];
    cm1 = cm[si + 8];
    {
        float4 e1 = cm0 ? make_float4(__expf(s1.x - msj.x), __expf(s1.y - msj.y),
                                      __expf(s1.z - msj.z), __expf(s1.w - msj.w))
                        : make_float4(0.f, 0.f, 0.f, 0.f);
        float4 e2 = cm1 ? make_float4(__expf(s2.x - msj.x), __expf(s2.y - msj.y),
                                      __expf(s2.z - msj.z), __expf(s2.w - msj.w))
                        : make_float4(0.f, 0.f, 0.f, 0.f);
        *(float4*)&Ss[0][si][sj] = tf4(e1);
        *(float4*)&Ss[0][si + 8][sj] = tf4(e2);
        *(float4*)&Cs[0][ci][ch] = tf4(c1);
        *(float4*)&Cs[0][ci][ch + 4] = tf4(c2);
    }
    __syncthreads();

    float acc[2][8][4] = {};
    for (int kk = 0; kk < CL; kk += 16) {
        int cur = (kk >> 4) & 1;
        bool more = (kk + 16) < CL;
        if (more) {
            int k2 = kk + 16;
            s1 = *(const float4*)(Sb + (size_t)(k2 + si) * QL + sj);
            s2 = *(const float4*)(Sb + (size_t)(k2 + si + 8) * QL + sj);
            c1 = *(const float4*)(Cb + (size_t)(k2 + ci) * HH + h0 + ch);
            c2 = *(const float4*)(Cb + (size_t)(k2 + ci) * HH + h0 + ch + 4);
            cm0 = cm[k2 + si];
            cm1 = cm[k2 + si + 8];
        }
#pragma unroll
        for (int h = 0; h < 2; h++) {
            int ck = h * 8 + c;
            uint32_t af[2][4], bf[8][2];
#pragma unroll
            for (int mi = 0; mi < 2; mi++) {
                int mb = m0w + mi * 16;
                af[mi][0] = __float_as_uint(Ss[cur][ck][mb + r]);
                af[mi][1] = __float_as_uint(Ss[cur][ck][mb + r + 8]);
                af[mi][2] = __float_as_uint(Ss[cur][ck + 4][mb + r]);
                af[mi][3] = __float_as_uint(Ss[cur][ck + 4][mb + r + 8]);
            }
#pragma unroll
            for (int ni = 0; ni < 8; ni++) {
                int nb = n0w + ni * 8 + r;
                bf[ni][0] = __float_as_uint(Cs[cur][ck][nb]);
                bf[ni][1] = __float_as_uint(Cs[cur][ck + 4][nb]);
            }
#pragma unroll
            for (int mi = 0; mi < 2; mi++)
#pragma unroll
                for (int ni = 0; ni < 8; ni++) mma8(acc[mi][ni], af[mi], bf[ni]);
        }
        if (more) {
            int nxt = cur ^ 1;
            float4 e1 = cm0 ? make_float4(__expf(s1.x - msj.x), __expf(s1.y - msj.y),
                                          __expf(s1.z - msj.z), __expf(s1.w - msj.w))
                            : make_float4(0.f, 0.f, 0.f, 0.f);
            float4 e2 = cm1 ? make_float4(__expf(s2.x - msj.x), __expf(s2.y - msj.y),
                                          __expf(s2.z - msj.z), __expf(s2.w - msj.w))
                            : make_float4(0.f, 0.f, 0.f, 0.f);
            *(float4*)&Ss[nxt][si][sj] = tf4(e1);
            *(float4*)&Ss[nxt][si + 8][sj] = tf4(e2);
            *(float4*)&Cs[nxt][ci][ch] = tf4(c1);
            *(float4*)&Cs[nxt][ci][ch + 4] = tf4(c2);
        }
        __syncthreads();
    }
#pragma unroll
    for (int mi = 0; mi < 2; mi++)
#pragma unroll
        for (int dh = 0; dh < 2; dh++) {
            int jl = m0w + mi * 16 + r + dh * 8;
            float inv = sinv[jl];
            float* To = g_T + ((size_t)b * QL + jl) * HH + h0;
#pragma unroll
            for (int ni = 0; ni < 8; ni++) {
                int h = n0w + ni * 8 + (c << 1);
                *(float2*)(To + h) = make_float2(acc[mi][ni][dh * 2] * inv,
                                                 acc[mi][ni][dh * 2 + 1] * inv);
            }
        }
}

// ---------------------------------------------------------------------------
// K6: fused A = Srow@Q and Bm = Srow@T (K=128), writes concat output.
// tile 128(i) x 128(h). warps 4x2, warp 32x64. dynamic smem (55296 B).
// ---------------------------------------------------------------------------
#define K6_AS(bu, i, k) dsm[(bu) * 2560 + (i) * 20 + (k)]
#define K6_QS(bu, k, n) dsm[5120 + (bu) * 2176 + (k) * 136 + (n)]
#define K6_TS(bu, k, n) dsm[9472 + (bu) * 2176 + (k) * 136 + (n)]

__global__ __launch_bounds__(256) void k_out(const float* __restrict__ C,
                                             const float* __restrict__ Q,
                                             float* __restrict__ out) {
    extern __shared__ float dsm[];
    int b = blockIdx.z, i0 = blockIdx.x * 128, h0 = blockIdx.y * 128;
    int t = threadIdx.x, lane = t & 31, wid = t >> 5;
    int m0w = (wid & 3) * 32, n0w = (wid >> 2) * 64;
    int r = lane >> 2, c = lane & 3;
    const float* Sr = g_Srow + ((size_t)b * CL + i0) * QL;
    const float* Qb = Q + (size_t)b * QL * HH;
    const float* Tb = g_T + (size_t)b * QL * HH;
    int lr = t >> 1, lk = (t & 1) * 8;
    int ci = t >> 4, ch = (t & 15) * 8;

    float4 a1, a2, q1, q2, t1, t2;
    a1 = *(const float4*)(Sr + (size_t)lr * QL + lk);
    a2 = *(const float4*)(Sr + (size_t)lr * QL + lk + 4);
    q1 = *(const float4*)(Qb + (size_t)ci * HH + h0 + ch);
    q2 = *(const float4*)(Qb + (size_t)ci * HH + h0 + ch + 4);
    t1 = *(const float4*)(Tb + (size_t)ci * HH + h0 + ch);
    t2 = *(const float4*)(Tb + (size_t)ci * HH + h0 + ch + 4);
    *(float4*)&K6_AS(0, lr, lk) = tf4(a1);
    *(float4*)&K6_AS(0, lr, lk + 4) = tf4(a2);
    *(float4*)&K6_QS(0, ci, ch) = tf4(q1);
    *(float4*)&K6_QS(0, ci, ch + 4) = tf4(q2);
    *(float4*)&K6_TS(0, ci, ch) = tf4(t1);
    *(float4*)&K6_TS(0, ci, ch + 4) = tf4(t2);
    __syncthreads();

    float accA[2][8][4] = {}, accB[2][8][4] = {};
    for (int kk = 0; kk < QL; kk += 16) {
        int cur = (kk >> 4) & 1;
        bool more = (kk + 16) < QL;
        if (more) {
            int k2 = kk + 16;
            a1 = *(const float4*)(Sr + (size_t)lr * QL + k2 + lk);
            a2 = *(const float4*)(Sr + (size_t)lr * QL + k2 + lk + 4);
            q1 = *(const float4*)(Qb + (size_t)(k2 + ci) * HH + h0 + ch);
            q2 = *(const float4*)(Qb + (size_t)(k2 + ci) * HH + h0 + ch + 4);
            t1 = *(const float4*)(Tb + (size_t)(k2 + ci) * HH + h0 + ch);
            t2 = *(const float4*)(Tb + (size_t)(k2 + ci) * HH + h0 + ch + 4);
        }
#pragma unroll
        for (int h = 0; h < 2; h++) {
            int ck = h * 8 + c;
            uint32_t af[2][4], bq[8][2], bt[8][2];
#pragma unroll
            for (int mi = 0; mi < 2; mi++) {
                int mb = m0w + mi * 16;
                af[mi][0] = __float_as_uint(K6_AS(cur, mb + r, ck));
                af[mi][1] = __float_as_uint(K6_AS(cur, mb + r + 8, ck));
                af[mi][2] = __float_as_uint(K6_AS(cur, mb + r, ck + 4));
                af[mi][3] = __float_as_uint(K6_AS(cur, mb + r + 8, ck + 4));
            }
#pragma unroll
            for (int ni = 0; ni < 8; ni++) {
                int nb = n0w + ni * 8 + r;
                bq[ni][0] = __float_as_uint(K6_QS(cur, ck, nb));
                bq[ni][1] = __float_as_uint(K6_QS(cur, ck + 4, nb));
                bt[ni][0] = __float_as_uint(K6_TS(cur, ck, nb));
                bt[ni][1] = __float_as_uint(K6_TS(cur, ck + 4, nb));
            }
#pragma unroll
            for (int mi = 0; mi < 2; mi++)
#pragma unroll
                for (int ni = 0; ni < 8; ni++) {
                    mma8(accA[mi][ni], af[mi], bq[ni]);
                    mma8(accB[mi][ni], af[mi], bt[ni]);
                }
        }
        if (more) {
            int nxt = cur ^ 1;
            *(float4*)&K6_AS(nxt, lr, lk) = tf4(a1);
            *(float4*)&K6_AS(nxt, lr, lk + 4) = tf4(a2);
            *(float4*)&K6_QS(nxt, ci, ch) = tf4(q1);
            *(float4*)&K6_QS(nxt, ci, ch + 4) = tf4(q2);
            *(float4*)&K6_TS(nxt, ci, ch) = tf4(t1);
            *(float4*)&K6_TS(nxt, ci, ch + 4) = tf4(t2);
        }
        __syncthreads();
    }
    const float* Cb = C + (size_t)b * CL * HH;
#pragma unroll
    for (int mi = 0; mi < 2; mi++)
#pragma unroll
        for (int dh = 0; dh < 2; dh++) {
            int i = i0 + m0w + mi * 16 + r + dh * 8;
            const float* Crow = Cb + (size_t)i * HH;
            float* ob = out + ((size_t)b * CL + i) * (4 * HH);
#pragma unroll
            for (int ni = 0; ni < 8; ni++) {
                int h = h0 + n0w + ni * 8 + (c << 1);
                float2 cv = *(const float2*)(Crow + h);
                float2 av = make_float2(accA[mi][ni][dh * 2], accA[mi][ni][dh * 2 + 1]);
                float2 bv = make_float2(accB[mi][ni][dh * 2], accB[mi][ni][dh * 2 + 1]);
                *(float2*)(ob + h) = cv;
                *(float2*)(ob + HH + h) = av;
                *(float2*)(ob + 2 * HH + h) = make_float2(cv.x * av.x, cv.y * av.y);
                *(float2*)(ob + 3 * HH + h) = make_float2(cv.x * bv.x, cv.y * bv.y);
            }
        }
}

// ---------------------------------------------------------------------------
extern "C" void kernel_launch(void* const* d_in, const int* in_sizes, int n_in,
                              void* d_out, int out_size) {
    const float* C = (const float*)d_in[0];
    const float* Q = (const float*)d_in[1];
    const int* cmask = (const int*)d_in[2];
    const int* qmask = (const int*)d_in[3];
    const float* w = (const float*)d_in[4];
    const float* bias = (const float*)d_in[5];
    float* out = (float*)d_out;

    static bool attr_done = false;
    if (!attr_done) {
        cudaFuncSetAttribute(k_out, cudaFuncAttributeMaxDynamicSharedMemorySize, 55296);
        attr_done = true;
    }

    k_sgemm<<<dim3(8, 1, BB), 256>>>(C, Q, w, bias, qmask);
    k_colsm<<<dim3(QL / 32, BB), dim3(32, 16)>>>(cmask);
    k_tgemm<<<dim3(1, 4, BB), 256>>>(C, cmask);
    k_out<<<dim3(8, 4, BB), 256, 55296>>>(C, Q, out);
}